// round 9
// baseline (speedup 1.0000x reference)
#include <cuda_runtime.h>
#include <mma.h>
#include <cstdint>
#include <math.h>

#define BB 64
#define SS 96
#define HH 1024
#define EE 512
#define VV 32000
#define TT 32
#define G3 3072
#define NT 128                // N tile per CTA
#define KC 32                 // K chunk (floats)
#define NBLK 250              // VV / NT
#define LDS 36                // smem leading dim (floats), 144B = 16B-multiple
// smem float offsets
#define OF_AHI 0
#define OF_ALO (64 * LDS)
#define OF_WHI (128 * LDS)
#define OF_WLO (OF_WHI + 128 * LDS)
#define SMF (OF_WLO + 128 * LDS)          // 13824 floats
#define DSMEM_BYTES (SMF * 4)             // 55296 B

using namespace nvcuda;

// ---------------- device scratch ----------------
__device__ float g_u[HH];
__device__ float g_ctx[BB * HH];
__device__ float g_gictx[BB * G3];
__device__ float g_giacc[BB * G3];
__device__ float g_ghacc[BB * G3];
__device__ float g_h[2][BB * HH];
__device__ float g_emb[BB * EE];          // relu(emb_table[tok]) fp32
__device__ int   g_tok[BB];
__device__ float g_pv[BB * NBLK];
__device__ int   g_pi[BB * NBLK];

// ---------------- helpers ----------------
__device__ __forceinline__ float to_tf32(float v) {
    float r;
    asm("cvt.rna.tf32.f32 %0, %1;" : "=f"(r) : "f"(v));
    return r;
}

// ---------------- init ----------------
__global__ void k_init(const float* __restrict__ eh, const float* __restrict__ embt) {
    int i = blockIdx.x * blockDim.x + threadIdx.x;
    if (i < BB * HH) g_h[0][i] = eh[i];
    if (i < BB)      g_tok[i] = 1;
    if (i < BB * EE) {
        int k = i & 511;
        g_emb[i] = fmaxf(embt[EE + k], 0.f);   // START_TOKEN = 1
    }
}

// ---------------- u = Ua^T Va ----------------
__global__ void __launch_bounds__(256) k_u(const float* __restrict__ Ua,
                                           const float* __restrict__ Va) {
    __shared__ float sva[HH];
    for (int i = threadIdx.x; i < HH; i += 256) sva[i] = Va[i];
    __syncthreads();
    int h = blockIdx.x * 256 + threadIdx.x;
    float acc = 0.f;
    for (int g = 0; g < HH; ++g) acc = fmaf(sva[g], Ua[(size_t)g * HH + h], acc);
    g_u[h] = acc;
}

// ---------------- attention (step-invariant) ----------------
__global__ void __launch_bounds__(128) k_attn(const float* __restrict__ keys,
                                              float* __restrict__ out_attn) {
    __shared__ float s_w[SS];
    __shared__ float s_u[HH];
    int b = blockIdx.x, tid = threadIdx.x;
    for (int i = tid; i < HH; i += 128) s_u[i] = g_u[i];
    __syncthreads();
    int warp = tid >> 5, lane = tid & 31;
    const float* kb = keys + (size_t)b * SS * HH;
    for (int s = warp; s < SS; s += 4) {
        const float* kr = kb + (size_t)s * HH;
        float acc = 0.f;
        for (int k = lane; k < HH; k += 32) acc = fmaf(kr[k], s_u[k], acc);
        #pragma unroll
        for (int o = 16; o; o >>= 1) acc += __shfl_down_sync(0xffffffffu, acc, o);
        if (!lane) s_w[s] = acc;
    }
    __syncthreads();
    if (warp == 0) {
        float m = -1e30f;
        for (int s = lane; s < SS; s += 32) m = fmaxf(m, s_w[s]);
        #pragma unroll
        for (int o = 16; o; o >>= 1) m = fmaxf(m, __shfl_xor_sync(0xffffffffu, m, o));
        float sum = 0.f;
        for (int s = lane; s < SS; s += 32) { float e = expf(s_w[s] - m); s_w[s] = e; sum += e; }
        #pragma unroll
        for (int o = 16; o; o >>= 1) sum += __shfl_xor_sync(0xffffffffu, sum, o);
        float inv = 1.f / sum;
        for (int s = lane; s < SS; s += 32) s_w[s] *= inv;
    }
    __syncthreads();
    for (int h = tid; h < HH; h += 128) {
        float acc = 0.f;
        for (int s = 0; s < SS; ++s) acc = fmaf(s_w[s], kb[(size_t)s * HH + h], acc);
        g_ctx[b * HH + h] = acc;
    }
    float* oa = out_attn + (size_t)b * TT * SS;
    for (int e = tid; e < TT * SS; e += 128) oa[e] = s_w[e % SS];
}

// ============ split-TF32 GEMM core: [64, NT=128] = A[64,K] @ W[n0..n0+127, K]^T ============
// 3xTF32 into one fp32 accumulator: acc += aHi*wHi + aHi*wLo + aLo*wHi (R8-validated math).
// Register-prefetch double buffering hides global latency under wmma compute.
__device__ __forceinline__ void mm_core(
    const float* __restrict__ A, int lda,
    const float* __restrict__ W, int ldw, int woff,
    int NC, int n0,
    float* __restrict__ outAcc,                        // gates mode: [64, G3] at col n0
    const float* __restrict__ bias, float* __restrict__ outL, int t, int bx)  // logits mode
{
    extern __shared__ float sm[];
    const int tid = threadIdx.x;           // 256 threads, 8 warps
    const int wid = tid >> 5;
    const int wm = wid >> 2, wn = wid & 3; // 2x4 warp grid over 64x128
    const int r6 = tid >> 3, c4 = (tid & 7) * 4;

    wmma::fragment<wmma::accumulator, 16, 16, 8, float> acc[2][2];
    #pragma unroll
    for (int mt = 0; mt < 2; ++mt)
        #pragma unroll
        for (int nt = 0; nt < 2; ++nt) wmma::fill_fragment(acc[mt][nt], 0.f);

    float4 pA[2], pW[4];
    // prefetch chunk 0
    {
        #pragma unroll
        for (int q = 0; q < 2; ++q) {
            int r = r6 + q * 32;
            pA[q] = *(const float4*)(A + (size_t)r * lda + c4);
        }
        #pragma unroll
        for (int q = 0; q < 4; ++q) {
            int r = r6 + q * 32;
            pW[q] = *(const float4*)(W + (size_t)(n0 + r) * ldw + woff + c4);
        }
    }

    for (int j = 0; j < NC; ++j) {
        // split prefetched regs into smem hi/lo
        #pragma unroll
        for (int q = 0; q < 2; ++q) {
            int r = r6 + q * 32;
            float4 v = pA[q], hi, lo;
            hi.x = to_tf32(v.x); lo.x = to_tf32(v.x - hi.x);
            hi.y = to_tf32(v.y); lo.y = to_tf32(v.y - hi.y);
            hi.z = to_tf32(v.z); lo.z = to_tf32(v.z - hi.z);
            hi.w = to_tf32(v.w); lo.w = to_tf32(v.w - hi.w);
            *(float4*)(sm + OF_AHI + r * LDS + c4) = hi;
            *(float4*)(sm + OF_ALO + r * LDS + c4) = lo;
        }
        #pragma unroll
        for (int q = 0; q < 4; ++q) {
            int r = r6 + q * 32;
            float4 v = pW[q], hi, lo;
            hi.x = to_tf32(v.x); lo.x = to_tf32(v.x - hi.x);
            hi.y = to_tf32(v.y); lo.y = to_tf32(v.y - hi.y);
            hi.z = to_tf32(v.z); lo.z = to_tf32(v.z - hi.z);
            hi.w = to_tf32(v.w); lo.w = to_tf32(v.w - hi.w);
            *(float4*)(sm + OF_WHI + r * LDS + c4) = hi;
            *(float4*)(sm + OF_WLO + r * LDS + c4) = lo;
        }
        __syncthreads();

        // issue next chunk's global loads (latency overlaps compute below)
        if (j + 1 < NC) {
            int k0 = (j + 1) * KC;
            #pragma unroll
            for (int q = 0; q < 2; ++q) {
                int r = r6 + q * 32;
                pA[q] = *(const float4*)(A + (size_t)r * lda + k0 + c4);
            }
            #pragma unroll
            for (int q = 0; q < 4; ++q) {
                int r = r6 + q * 32;
                pW[q] = *(const float4*)(W + (size_t)(n0 + r) * ldw + woff + k0 + c4);
            }
        }

        #pragma unroll
        for (int kk = 0; kk < KC / 8; ++kk) {
            wmma::fragment<wmma::matrix_a, 16, 16, 8, wmma::precision::tf32, wmma::row_major> faH[2], faL[2];
            #pragma unroll
            for (int mt = 0; mt < 2; ++mt) {
                int mr = wm * 32 + mt * 16;
                wmma::load_matrix_sync(faH[mt], sm + OF_AHI + mr * LDS + kk * 8, LDS);
                wmma::load_matrix_sync(faL[mt], sm + OF_ALO + mr * LDS + kk * 8, LDS);
            }
            #pragma unroll
            for (int nt = 0; nt < 2; ++nt) {
                int nc = wn * 32 + nt * 16;
                wmma::fragment<wmma::matrix_b, 16, 16, 8, wmma::precision::tf32, wmma::col_major> fbH, fbL;
                wmma::load_matrix_sync(fbH, sm + OF_WHI + nc * LDS + kk * 8, LDS);
                wmma::load_matrix_sync(fbL, sm + OF_WLO + nc * LDS + kk * 8, LDS);
                #pragma unroll
                for (int mt = 0; mt < 2; ++mt) {
                    wmma::mma_sync(acc[mt][nt], faH[mt], fbH, acc[mt][nt]);
                    wmma::mma_sync(acc[mt][nt], faH[mt], fbL, acc[mt][nt]);
                    wmma::mma_sync(acc[mt][nt], faL[mt], fbH, acc[mt][nt]);
                }
            }
        }
        __syncthreads();
    }

    // ---- epilogue: accumulators -> smem [64][128] ----
    float* sbuf = sm;
    #pragma unroll
    for (int mt = 0; mt < 2; ++mt)
        #pragma unroll
        for (int nt = 0; nt < 2; ++nt)
            wmma::store_matrix_sync(sbuf + (wm * 32 + mt * 16) * NT + wn * 32 + nt * 16,
                                    acc[mt][nt], NT, wmma::mem_row_major);
    __syncthreads();

    if (outAcc) {   // gates mode: write [64, G3] block at column n0
        for (int i = tid; i < 64 * NT; i += 256) {
            int b = i >> 7, n = i & 127;
            outAcc[(size_t)b * G3 + n0 + n] = sbuf[i];
        }
        return;
    }

    // logits mode: bias + store + per-row argmax partial
    int b = tid >> 2, cs = (tid & 3) * 32;
    float* out = outL + (size_t)b * TT * VV + (size_t)t * VV + n0;
    float bestv = -1e30f; int besti = 0;
    #pragma unroll
    for (int n = cs; n < cs + 32; n += 4) {
        float4 v = *(float4*)&sbuf[b * NT + n];
        float4 bi = *(const float4*)&bias[n0 + n];
        v.x += bi.x; v.y += bi.y; v.z += bi.z; v.w += bi.w;
        *(float4*)(out + n) = v;
        if (v.x > bestv) { bestv = v.x; besti = n0 + n; }
        if (v.y > bestv) { bestv = v.y; besti = n0 + n + 1; }
        if (v.z > bestv) { bestv = v.z; besti = n0 + n + 2; }
        if (v.w > bestv) { bestv = v.w; besti = n0 + n + 3; }
    }
    #pragma unroll
    for (int o = 1; o <= 2; o <<= 1) {
        float ov = __shfl_xor_sync(0xffffffffu, bestv, o);
        int   oi = __shfl_xor_sync(0xffffffffu, besti, o);
        if (ov > bestv || (ov == bestv && oi < besti)) { bestv = ov; besti = oi; }
    }
    if ((tid & 3) == 0) {
        g_pv[b * NBLK + bx] = bestv;
        g_pi[b * NBLK + bx] = besti;
    }
}

__global__ void __launch_bounds__(256, 2) k_mm_logits(int hsel,
        const float* __restrict__ W_out, const float* __restrict__ b_out,
        float* __restrict__ outL, int t) {
    mm_core(g_h[hsel], HH, W_out, HH, 0, HH / KC, blockIdx.x * NT,
            nullptr, b_out, outL, t, blockIdx.x);
}
__global__ void __launch_bounds__(256, 2) k_mm_pre(int cur,
        const float* __restrict__ W_ih, const float* __restrict__ W_hh) {
    int bx = blockIdx.x;
    if (bx < 24)
        mm_core(g_h[cur], HH, W_hh, HH, 0, HH / KC, bx * NT,
                g_ghacc, nullptr, nullptr, 0, 0);
    else
        mm_core(g_emb, EE, W_ih, EE + HH, 0, EE / KC, (bx - 24) * NT,
                g_giacc, nullptr, nullptr, 0, 0);
}
__global__ void __launch_bounds__(256, 2) k_mm_gictx(const float* __restrict__ W_ih) {
    mm_core(g_ctx, HH, W_ih, EE + HH, EE, HH / KC, blockIdx.x * NT,
            g_gictx, nullptr, nullptr, 0, 0);
}

// ---------------- GRU gates (R2 exact) ----------------
__global__ void __launch_bounds__(256) k_gates(int cur,
        const float* __restrict__ b_ih, const float* __restrict__ b_hh,
        float* __restrict__ out_h) {
    int idx = blockIdx.x * 256 + threadIdx.x;
    int b = idx >> 10, i = idx & 1023;
    int base = b * G3;
    float gir = g_giacc[base + i]        + g_gictx[base + i]        + b_ih[i];
    float giz = g_giacc[base + 1024 + i] + g_gictx[base + 1024 + i] + b_ih[1024 + i];
    float gin = g_giacc[base + 2048 + i] + g_gictx[base + 2048 + i] + b_ih[2048 + i];
    float ghr = g_ghacc[base + i]        + b_hh[i];
    float ghz = g_ghacc[base + 1024 + i] + b_hh[1024 + i];
    float ghn = g_ghacc[base + 2048 + i] + b_hh[2048 + i];
    float r = 1.f / (1.f + expf(-(gir + ghr)));
    float z = 1.f / (1.f + expf(-(giz + ghz)));
    float n = tanhf(gin + r * ghn);
    float h = g_h[cur][idx];
    float hn = (1.f - z) * n + z * h;
    g_h[cur ^ 1][idx] = hn;
    if (out_h) out_h[idx] = hn;
}

// ---------------- argmax finalize -> token + emb gather ----------------
__global__ void __launch_bounds__(256) k_amax_fin(const float* __restrict__ embt) {
    int b = blockIdx.x, tid = threadIdx.x;
    float v = -1e30f; int i = 0x7fffffff;
    for (int p = tid; p < NBLK; p += 256) {
        float pv = g_pv[b * NBLK + p]; int pi = g_pi[b * NBLK + p];
        if (pv > v || (pv == v && pi < i)) { v = pv; i = pi; }
    }
    __shared__ float sv[256]; __shared__ int si[256];
    sv[tid] = v; si[tid] = i; __syncthreads();
    for (int s = 128; s; s >>= 1) {
        if (tid < s && (sv[tid + s] > sv[tid] ||
                        (sv[tid + s] == sv[tid] && si[tid + s] < si[tid]))) {
            sv[tid] = sv[tid + s]; si[tid] = si[tid + s];
        }
        __syncthreads();
    }
    if (!tid) g_tok[b] = si[0];
    __syncthreads();
    int tok = si[0];
    for (int k = tid; k < EE; k += 256)
        g_emb[b * EE + k] = fmaxf(embt[(size_t)tok * EE + k], 0.f);
}

// ---------------- host ----------------
extern "C" void kernel_launch(void* const* d_in, const int* in_sizes, int n_in,
                              void* d_out, int out_size) {
    const float* enc   = (const float*)d_in[0];
    const float* eh    = (const float*)d_in[1];
    const float* embt  = (const float*)d_in[2];
    // d_in[3] = Wa: dead code (softmax shift invariance)
    const float* Ua    = (const float*)d_in[4];
    const float* Va    = (const float*)d_in[5];
    const float* W_ih  = (const float*)d_in[6];
    const float* W_hh  = (const float*)d_in[7];
    const float* b_ih  = (const float*)d_in[8];
    const float* b_hh  = (const float*)d_in[9];
    const float* W_out = (const float*)d_in[10];
    const float* b_out = (const float*)d_in[11];

    float* outL = (float*)d_out;
    float* outH = outL + (size_t)BB * TT * VV;
    float* outA = outH + (size_t)BB * HH;

    cudaFuncSetAttribute(k_mm_logits, cudaFuncAttributeMaxDynamicSharedMemorySize, DSMEM_BYTES);
    cudaFuncSetAttribute(k_mm_pre,    cudaFuncAttributeMaxDynamicSharedMemorySize, DSMEM_BYTES);
    cudaFuncSetAttribute(k_mm_gictx,  cudaFuncAttributeMaxDynamicSharedMemorySize, DSMEM_BYTES);

    k_init<<<(BB * HH + 255) / 256, 256>>>(eh, embt);
    k_u<<<HH / 256, 256>>>(Ua, Va);
    k_attn<<<BB, 128>>>(enc, outA);
    k_mm_gictx<<<G3 / NT, 256, DSMEM_BYTES>>>(W_ih);

    for (int t = 0; t < TT; ++t) {
        int cur = t & 1;
        k_mm_pre<<<2 * (G3 / NT), 256, DSMEM_BYTES>>>(cur, W_ih, W_hh);
        k_gates<<<BB * HH / 256, 256>>>(cur, b_ih, b_hh, (t == TT - 1) ? outH : nullptr);
        k_mm_logits<<<NBLK, 256, DSMEM_BYTES>>>(cur ^ 1, W_out, b_out, outL, t);
        if (t < TT - 1) k_amax_fin<<<BB, 256>>>(embt);
    }
}

// round 11
// speedup vs baseline: 1.1221x; 1.1221x over previous
#include <cuda_runtime.h>
#include <mma.h>
#include <cstdint>
#include <math.h>

#define BB 64
#define SS 96
#define HH 1024
#define EE 512
#define VV 32000
#define TT 32
#define G3 3072
#define CTAN 128              // N tile per CTA
#define KC 32                 // K chunk (floats)
#define NBLK 250              // VV / CTAN
#define LDS 36                // smem row stride (floats)
// raw stage: A[64x36]=2304 + W[128x36]=4608 = 6912 floats; two stages
#define RAW_W   2304
#define RAW_FL  6912
// split buffer at 13824: Ahi 0 / Alo 2304 / Whi 4608 / Wlo 9216 (floats, rel.)
#define SPL     13824
#define SP_ALO  2304
#define SP_WHI  4608
#define SP_WLO  9216
#define SM_FL   (SPL + 13824)             // 27648 floats
#define DSMEM_BYTES (SM_FL * 4)           // 110592 B

using namespace nvcuda;

// ---------------- device scratch (small only — no big prologue-written arrays!) ----------------
__device__ float g_u[HH];
__device__ float g_ctx[BB * HH];
__device__ float g_gictx[BB * G3];
__device__ float g_giacc[BB * G3];
__device__ float g_ghA[BB * G3];
__device__ float g_ghB[BB * G3];
__device__ float g_h[BB * HH];
__device__ float g_emb[BB * EE];
__device__ int   g_tok[BB];
__device__ float g_pv[BB * NBLK];
__device__ int   g_pi[BB * NBLK];

// ---------------- helpers ----------------
__device__ __forceinline__ float to_tf32(float v) {
    float r;
    asm("cvt.rna.tf32.f32 %0, %1;" : "=f"(r) : "f"(v));
    return r;
}
__device__ __forceinline__ uint32_t smem_u32(const void* p) {
    uint32_t a;
    asm("{ .reg .u64 t; cvta.to.shared.u64 t, %1; cvt.u32.u64 %0, t; }" : "=r"(a) : "l"(p));
    return a;
}
#define CPA16(sa, ga) \
    asm volatile("cp.async.cg.shared.global [%0], [%1], 16;" :: "r"(sa), "l"(ga))

// ---------------- init ----------------
__global__ void k_init(const float* __restrict__ eh, const float* __restrict__ embt) {
    int i = blockIdx.x * blockDim.x + threadIdx.x;
    if (i < BB * HH) g_h[i] = eh[i];
    if (i < BB)      g_tok[i] = 1;
    if (i < BB * EE) g_emb[i] = fmaxf(embt[EE + (i & 511)], 0.f);   // START_TOKEN = 1
}

// ---------------- u = Ua^T Va ----------------
__global__ void __launch_bounds__(256) k_u(const float* __restrict__ Ua,
                                           const float* __restrict__ Va) {
    __shared__ float sva[HH];
    for (int i = threadIdx.x; i < HH; i += 256) sva[i] = Va[i];
    __syncthreads();
    int h = blockIdx.x * 256 + threadIdx.x;
    float acc = 0.f;
    for (int g = 0; g < HH; ++g) acc = fmaf(sva[g], Ua[(size_t)g * HH + h], acc);
    g_u[h] = acc;
}

// ---------------- attention (step-invariant) ----------------
__global__ void __launch_bounds__(128) k_attn(const float* __restrict__ keys,
                                              float* __restrict__ out_attn) {
    __shared__ float s_w[SS];
    __shared__ float s_u[HH];
    int b = blockIdx.x, tid = threadIdx.x;
    for (int i = tid; i < HH; i += 128) s_u[i] = g_u[i];
    __syncthreads();
    int warp = tid >> 5, lane = tid & 31;
    const float* kb = keys + (size_t)b * SS * HH;
    for (int s = warp; s < SS; s += 4) {
        const float* kr = kb + (size_t)s * HH;
        float acc = 0.f;
        for (int k = lane; k < HH; k += 32) acc = fmaf(kr[k], s_u[k], acc);
        #pragma unroll
        for (int o = 16; o; o >>= 1) acc += __shfl_down_sync(0xffffffffu, acc, o);
        if (!lane) s_w[s] = acc;
    }
    __syncthreads();
    if (warp == 0) {
        float m = -1e30f;
        for (int s = lane; s < SS; s += 32) m = fmaxf(m, s_w[s]);
        #pragma unroll
        for (int o = 16; o; o >>= 1) m = fmaxf(m, __shfl_xor_sync(0xffffffffu, m, o));
        float sum = 0.f;
        for (int s = lane; s < SS; s += 32) { float e = expf(s_w[s] - m); s_w[s] = e; sum += e; }
        #pragma unroll
        for (int o = 16; o; o >>= 1) sum += __shfl_xor_sync(0xffffffffu, sum, o);
        float inv = 1.f / sum;
        for (int s = lane; s < SS; s += 32) s_w[s] *= inv;
    }
    __syncthreads();
    for (int h = tid; h < HH; h += 128) {
        float acc = 0.f;
        for (int s = 0; s < SS; ++s) acc = fmaf(s_w[s], kb[(size_t)s * HH + h], acc);
        g_ctx[b * HH + h] = acc;
    }
    float* oa = out_attn + (size_t)b * TT * SS;
    for (int e = tid; e < TT * SS; e += 128) oa[e] = s_w[e % SS];
}

// ============ split-TF32 GEMM core (raw fp32 inputs, in-kernel split, cp.async) ============
// out[64, 128] = A[64,K] @ W[n0..n0+127, :]^T.  3xTF32: acc += aH*wH + aH*wL + aL*wH
// (R8/R9-validated math).  256 threads = 8 warps in 2(m)x4(n), warp tile 32x32.
__device__ __forceinline__ void mm_core(
    const float* __restrict__ A, int lda,
    const float* __restrict__ W, int ldw,
    int NC, int n0,
    float* __restrict__ outAcc,                                        // gates mode
    const float* __restrict__ bias, float* __restrict__ outL, int t, int bx)  // logits mode
{
    extern __shared__ float sm[];
    const int tid = threadIdx.x;
    const int wid = tid >> 5;
    const int wm = wid >> 2, wn = wid & 3;
    const uint32_t smu = smem_u32(sm);

    wmma::fragment<wmma::accumulator, 16, 16, 8, float> acc[2][2];
    #pragma unroll
    for (int mt = 0; mt < 2; ++mt)
        #pragma unroll
        for (int nt = 0; nt < 2; ++nt) wmma::fill_fragment(acc[mt][nt], 0.f);

    auto load_stage = [&](int j) {
        const uint32_t base = smu + ((j & 1) * RAW_FL) * 4;
        int k0 = j * KC;
        #pragma unroll
        for (int q = 0; q < 2; ++q) {               // A: 512 tasks of 16B
            int i = q * 256 + tid;
            int r = i >> 3, s = i & 7;
            CPA16(base + (r * LDS + s * 4) * 4, A + (size_t)r * lda + k0 + s * 4);
        }
        #pragma unroll
        for (int q = 0; q < 4; ++q) {               // W: 1024 tasks of 16B
            int i = q * 256 + tid;
            int r = i >> 3, s = i & 7;
            CPA16(base + (RAW_W + r * LDS + s * 4) * 4,
                  W + (size_t)(n0 + r) * ldw + k0 + s * 4);
        }
        asm volatile("cp.async.commit_group;" ::: "memory");
    };

    load_stage(0);
    if (NC > 1) load_stage(1);

    for (int j = 0; j < NC; ++j) {
        if (j + 1 < NC) asm volatile("cp.async.wait_group 1;" ::: "memory");
        else            asm volatile("cp.async.wait_group 0;" ::: "memory");
        __syncthreads();

        // split raw[j&1] -> SPL hi/lo (pads included, never read by wmma)
        const float* raw = sm + (j & 1) * RAW_FL;
        float* spl = sm + SPL;
        #pragma unroll
        for (int q = 0; q < 27; ++q) {
            int i = q * 256 + tid;
            if (i < RAW_FL) {
                float v = raw[i];
                float hi = to_tf32(v);
                float lo = to_tf32(v - hi);
                if (i < RAW_W) { spl[i] = hi;                    spl[SP_ALO + i] = lo; }
                else { int iw = i - RAW_W; spl[SP_WHI + iw] = hi; spl[SP_WLO + iw] = lo; }
            }
        }
        __syncthreads();

        if (j + 2 < NC) load_stage(j + 2);

        #pragma unroll
        for (int kk = 0; kk < KC / 8; ++kk) {
            wmma::fragment<wmma::matrix_a, 16, 16, 8, wmma::precision::tf32, wmma::row_major> aH[2], aL[2];
            #pragma unroll
            for (int mt = 0; mt < 2; ++mt) {
                int mr = wm * 32 + mt * 16;
                wmma::load_matrix_sync(aH[mt], spl + mr * LDS + kk * 8, LDS);
                wmma::load_matrix_sync(aL[mt], spl + SP_ALO + mr * LDS + kk * 8, LDS);
            }
            #pragma unroll
            for (int nt = 0; nt < 2; ++nt) {
                int nc = wn * 32 + nt * 16;
                wmma::fragment<wmma::matrix_b, 16, 16, 8, wmma::precision::tf32, wmma::col_major> bH, bL;
                wmma::load_matrix_sync(bH, spl + SP_WHI + nc * LDS + kk * 8, LDS);
                wmma::load_matrix_sync(bL, spl + SP_WLO + nc * LDS + kk * 8, LDS);
                #pragma unroll
                for (int mt = 0; mt < 2; ++mt) {
                    wmma::mma_sync(acc[mt][nt], aH[mt], bH, acc[mt][nt]);
                    wmma::mma_sync(acc[mt][nt], aH[mt], bL, acc[mt][nt]);
                    wmma::mma_sync(acc[mt][nt], aL[mt], bH, acc[mt][nt]);
                }
            }
        }
        __syncthreads();
    }

    // ---- epilogue: accumulators -> smem [64][128] (raw region, free now) ----
    float* sbuf = sm;
    #pragma unroll
    for (int mt = 0; mt < 2; ++mt)
        #pragma unroll
        for (int nt = 0; nt < 2; ++nt)
            wmma::store_matrix_sync(sbuf + (wm * 32 + mt * 16) * CTAN + wn * 32 + nt * 16,
                                    acc[mt][nt], CTAN, wmma::mem_row_major);
    __syncthreads();

    if (outAcc) {   // gates mode
        for (int i = tid; i < 64 * CTAN; i += 256) {
            int b = i >> 7, n = i & 127;
            outAcc[(size_t)b * G3 + n0 + n] = sbuf[i];
        }
        return;
    }

    // logits mode: bias + store + per-row argmax partial
    int b = tid >> 2, cs = (tid & 3) * 32;
    float* out = outL + (size_t)b * TT * VV + (size_t)t * VV + n0;
    float bestv = -1e30f; int besti = 0;
    #pragma unroll
    for (int n = cs; n < cs + 32; n += 4) {
        float4 v = *(float4*)&sbuf[b * CTAN + n];
        float4 bi = *(const float4*)&bias[n0 + n];
        v.x += bi.x; v.y += bi.y; v.z += bi.z; v.w += bi.w;
        *(float4*)(out + n) = v;
        if (v.x > bestv) { bestv = v.x; besti = n0 + n; }
        if (v.y > bestv) { bestv = v.y; besti = n0 + n + 1; }
        if (v.z > bestv) { bestv = v.z; besti = n0 + n + 2; }
        if (v.w > bestv) { bestv = v.w; besti = n0 + n + 3; }
    }
    #pragma unroll
    for (int o = 1; o <= 2; o <<= 1) {
        float ov = __shfl_xor_sync(0xffffffffu, bestv, o);
        int   oi = __shfl_xor_sync(0xffffffffu, besti, o);
        if (ov > bestv || (ov == bestv && oi < besti)) { bestv = ov; besti = oi; }
    }
    if ((tid & 3) == 0) {
        g_pv[b * NBLK + bx] = bestv;
        g_pi[b * NBLK + bx] = besti;
    }
}

__global__ void __launch_bounds__(256, 2) k_mm_logits(const float* __restrict__ W_out,
                                                      const float* __restrict__ b_out,
                                                      float* __restrict__ outL, int t) {
    mm_core(g_h, HH, W_out, HH, HH / KC, blockIdx.x * CTAN,
            nullptr, b_out, outL, t, blockIdx.x);
}
__global__ void __launch_bounds__(256, 2) k_mm_pre(const float* __restrict__ W_ih,
                                                   const float* __restrict__ W_hh) {
    int bx = blockIdx.x;   // 72 CTAs: [0,24) ghA (K 0-511), [24,48) ghB (K 512-1023), [48,72) gi
    if (bx < 24)
        mm_core(g_h, HH, W_hh, HH, 512 / KC, bx * CTAN,
                g_ghA, nullptr, nullptr, 0, 0);
    else if (bx < 48)
        mm_core(g_h + 512, HH, W_hh + 512, HH, 512 / KC, (bx - 24) * CTAN,
                g_ghB, nullptr, nullptr, 0, 0);
    else
        mm_core(g_emb, EE, W_ih, EE + HH, EE / KC, (bx - 48) * CTAN,
                g_giacc, nullptr, nullptr, 0, 0);
}
__global__ void __launch_bounds__(256, 2) k_mm_gictx(const float* __restrict__ W_ih) {
    mm_core(g_ctx, HH, W_ih + EE, EE + HH, HH / KC, blockIdx.x * CTAN,
            g_gictx, nullptr, nullptr, 0, 0);
}

// ---------------- GRU gates ----------------
__global__ void __launch_bounds__(256) k_gates(const float* __restrict__ b_ih,
                                               const float* __restrict__ b_hh,
                                               float* __restrict__ out_h) {
    int idx = blockIdx.x * 256 + threadIdx.x;   // < 65536
    int b = idx >> 10, i = idx & 1023;
    int base = b * G3;
    float gir = g_giacc[base + i]        + g_gictx[base + i]        + b_ih[i];
    float giz = g_giacc[base + 1024 + i] + g_gictx[base + 1024 + i] + b_ih[1024 + i];
    float gin = g_giacc[base + 2048 + i] + g_gictx[base + 2048 + i] + b_ih[2048 + i];
    float ghr = g_ghA[base + i]        + g_ghB[base + i]        + b_hh[i];
    float ghz = g_ghA[base + 1024 + i] + g_ghB[base + 1024 + i] + b_hh[1024 + i];
    float ghn = g_ghA[base + 2048 + i] + g_ghB[base + 2048 + i] + b_hh[2048 + i];
    float r = 1.f / (1.f + expf(-(gir + ghr)));
    float z = 1.f / (1.f + expf(-(giz + ghz)));
    float n = tanhf(gin + r * ghn);
    float hn = (1.f - z) * n + z * g_h[idx];
    g_h[idx] = hn;
    if (out_h) out_h[idx] = hn;
}

// ---------------- argmax finalize -> token + emb gather ----------------
__global__ void __launch_bounds__(256) k_amax_fin(const float* __restrict__ embt) {
    int b = blockIdx.x, tid = threadIdx.x;
    float v = -1e30f; int i = 0x7fffffff;
    for (int p = tid; p < NBLK; p += 256) {
        float pv = g_pv[b * NBLK + p]; int pi = g_pi[b * NBLK + p];
        if (pv > v || (pv == v && pi < i)) { v = pv; i = pi; }
    }
    __shared__ float sv[256]; __shared__ int si[256];
    sv[tid] = v; si[tid] = i; __syncthreads();
    for (int s = 128; s; s >>= 1) {
        if (tid < s && (sv[tid + s] > sv[tid] ||
                        (sv[tid + s] == sv[tid] && si[tid + s] < si[tid]))) {
            sv[tid] = sv[tid + s]; si[tid] = si[tid + s];
        }
        __syncthreads();
    }
    if (!tid) g_tok[b] = si[0];
    __syncthreads();
    int tok = si[0];
    for (int k = tid; k < EE; k += 256)
        g_emb[b * EE + k] = fmaxf(embt[(size_t)tok * EE + k], 0.f);
}

// ---------------- host ----------------
extern "C" void kernel_launch(void* const* d_in, const int* in_sizes, int n_in,
                              void* d_out, int out_size) {
    const float* enc   = (const float*)d_in[0];
    const float* eh    = (const float*)d_in[1];
    const float* embt  = (const float*)d_in[2];
    // d_in[3] = Wa: dead code (softmax shift invariance)
    const float* Ua    = (const float*)d_in[4];
    const float* Va    = (const float*)d_in[5];
    const float* W_ih  = (const float*)d_in[6];
    const float* W_hh  = (const float*)d_in[7];
    const float* b_ih  = (const float*)d_in[8];
    const float* b_hh  = (const float*)d_in[9];
    const float* W_out = (const float*)d_in[10];
    const float* b_out = (const float*)d_in[11];

    float* outL = (float*)d_out;
    float* outH = outL + (size_t)BB * TT * VV;
    float* outA = outH + (size_t)BB * HH;

    cudaFuncSetAttribute(k_mm_logits, cudaFuncAttributeMaxDynamicSharedMemorySize, DSMEM_BYTES);
    cudaFuncSetAttribute(k_mm_pre,    cudaFuncAttributeMaxDynamicSharedMemorySize, DSMEM_BYTES);
    cudaFuncSetAttribute(k_mm_gictx,  cudaFuncAttributeMaxDynamicSharedMemorySize, DSMEM_BYTES);

    k_init<<<(BB * HH + 255) / 256, 256>>>(eh, embt);
    k_u<<<HH / 256, 256>>>(Ua, Va);
    k_attn<<<BB, 128>>>(enc, outA);
    k_mm_gictx<<<G3 / CTAN, 256, DSMEM_BYTES>>>(W_ih);

    for (int t = 0; t < TT; ++t) {
        k_mm_pre<<<72, 256, DSMEM_BYTES>>>(W_ih, W_hh);
        k_gates<<<BB * HH / 256, 256>>>(b_ih, b_hh, (t == TT - 1) ? outH : nullptr);
        k_mm_logits<<<NBLK, 256, DSMEM_BYTES>>>(W_out, b_out, outL, t);
        if (t < TT - 1) k_amax_fin<<<BB, 256>>>(embt);
    }
}

// round 12
// speedup vs baseline: 1.2055x; 1.0743x over previous
#include <cuda_runtime.h>
#include <mma.h>
#include <cstdint>
#include <math.h>

#define BB 64
#define SS 96
#define HH 1024
#define EE 512
#define VV 32000
#define TT 32
#define G3 3072
#define CTAN 64               // N tile per CTA
#define KC 32                 // K chunk (floats)
#define NBLK 500              // VV / CTAN
#define LDS 36                // smem row stride (floats)
// raw stage: A[64x36]=2304 + W[64x36]=2304 = 4608 floats; two stages
#define RAW_W   2304
#define RAW_FL  4608
// split region at 9216: Ahi 0 / Alo 2304 / Whi 4608 / Wlo 6912 (floats, rel.)
#define SPL     9216
#define SP_ALO  2304
#define SP_WHI  4608
#define SP_WLO  6912
#define SM_FL   (SPL + 9216)              // 18432 floats
#define DSMEM_BYTES (SM_FL * 4)           // 73728 B -> 3 CTAs/SM

using namespace nvcuda;

// ---------------- device scratch (small, step-written only) ----------------
__device__ float g_u[HH];
__device__ float g_ctx[BB * HH];
__device__ float g_gictx[BB * G3];
__device__ float g_giacc[BB * G3];
__device__ float g_ghA[BB * G3];
__device__ float g_ghB[BB * G3];
__device__ float g_h[BB * HH];
__device__ float g_emb[BB * EE];
__device__ int   g_tok[BB];
__device__ float g_pv[BB * NBLK];
__device__ int   g_pi[BB * NBLK];

// ---------------- helpers ----------------
__device__ __forceinline__ float to_tf32(float v) {
    float r;
    asm("cvt.rna.tf32.f32 %0, %1;" : "=f"(r) : "f"(v));
    return r;
}
__device__ __forceinline__ uint32_t smem_u32(const void* p) {
    uint32_t a;
    asm("{ .reg .u64 t; cvta.to.shared.u64 t, %1; cvt.u32.u64 %0, t; }" : "=r"(a) : "l"(p));
    return a;
}
#define CPA16(sa, ga) \
    asm volatile("cp.async.cg.shared.global [%0], [%1], 16;" :: "r"(sa), "l"(ga))

__device__ __forceinline__ void split4(float4 v, float4* hi, float4* lo) {
    hi->x = to_tf32(v.x); lo->x = to_tf32(v.x - hi->x);
    hi->y = to_tf32(v.y); lo->y = to_tf32(v.y - hi->y);
    hi->z = to_tf32(v.z); lo->z = to_tf32(v.z - hi->z);
    hi->w = to_tf32(v.w); lo->w = to_tf32(v.w - hi->w);
}

// ---------------- init ----------------
__global__ void k_init(const float* __restrict__ eh, const float* __restrict__ embt) {
    int i = blockIdx.x * blockDim.x + threadIdx.x;
    if (i < BB * HH) g_h[i] = eh[i];
    if (i < BB)      g_tok[i] = 1;
    if (i < BB * EE) g_emb[i] = fmaxf(embt[EE + (i & 511)], 0.f);   // START_TOKEN = 1
}

// ---------------- u = Ua^T Va ----------------
__global__ void __launch_bounds__(256) k_u(const float* __restrict__ Ua,
                                           const float* __restrict__ Va) {
    __shared__ float sva[HH];
    for (int i = threadIdx.x; i < HH; i += 256) sva[i] = Va[i];
    __syncthreads();
    int h = blockIdx.x * 256 + threadIdx.x;
    float acc = 0.f;
    for (int g = 0; g < HH; ++g) acc = fmaf(sva[g], Ua[(size_t)g * HH + h], acc);
    g_u[h] = acc;
}

// ---------------- attention (step-invariant) ----------------
__global__ void __launch_bounds__(128) k_attn(const float* __restrict__ keys,
                                              float* __restrict__ out_attn) {
    __shared__ float s_w[SS];
    __shared__ float s_u[HH];
    int b = blockIdx.x, tid = threadIdx.x;
    for (int i = tid; i < HH; i += 128) s_u[i] = g_u[i];
    __syncthreads();
    int warp = tid >> 5, lane = tid & 31;
    const float* kb = keys + (size_t)b * SS * HH;
    for (int s = warp; s < SS; s += 4) {
        const float* kr = kb + (size_t)s * HH;
        float acc = 0.f;
        for (int k = lane; k < HH; k += 32) acc = fmaf(kr[k], s_u[k], acc);
        #pragma unroll
        for (int o = 16; o; o >>= 1) acc += __shfl_down_sync(0xffffffffu, acc, o);
        if (!lane) s_w[s] = acc;
    }
    __syncthreads();
    if (warp == 0) {
        float m = -1e30f;
        for (int s = lane; s < SS; s += 32) m = fmaxf(m, s_w[s]);
        #pragma unroll
        for (int o = 16; o; o >>= 1) m = fmaxf(m, __shfl_xor_sync(0xffffffffu, m, o));
        float sum = 0.f;
        for (int s = lane; s < SS; s += 32) { float e = expf(s_w[s] - m); s_w[s] = e; sum += e; }
        #pragma unroll
        for (int o = 16; o; o >>= 1) sum += __shfl_xor_sync(0xffffffffu, sum, o);
        float inv = 1.f / sum;
        for (int s = lane; s < SS; s += 32) s_w[s] *= inv;
    }
    __syncthreads();
    for (int h = tid; h < HH; h += 128) {
        float acc = 0.f;
        for (int s = 0; s < SS; ++s) acc = fmaf(s_w[s], kb[(size_t)s * HH + h], acc);
        g_ctx[b * HH + h] = acc;
    }
    float* oa = out_attn + (size_t)b * TT * SS;
    for (int e = tid; e < TT * SS; e += 128) oa[e] = s_w[e % SS];
}

// ============ split-TF32 GEMM core (R11 math/dataflow, re-tiled 64x64, 3 CTAs/SM) ============
// out[64, 64] = A[64,K] @ W[n0..n0+63, :]^T.  3xTF32: acc += aH*wH + aH*wL + aL*wH.
// 256 threads = 8 warps in 2(m)x4(n), warp tile 32x16.
__device__ __forceinline__ void mm_core(
    const float* __restrict__ A, int lda,
    const float* __restrict__ W, int ldw,
    int NC, int n0,
    float* __restrict__ outAcc,                                        // gates mode
    const float* __restrict__ bias, float* __restrict__ outL, int t, int bx)  // logits mode
{
    extern __shared__ float sm[];
    const int tid = threadIdx.x;
    const int wid = tid >> 5;
    const int wm = wid >> 2, wn = wid & 3;
    const uint32_t smu = smem_u32(sm);
    const int r8 = tid >> 3, s4 = (tid & 7) * 4;   // load/split lane mapping
    const int loff = r8 * LDS + s4;

    wmma::fragment<wmma::accumulator, 16, 16, 8, float> acc[2];
    wmma::fill_fragment(acc[0], 0.f);
    wmma::fill_fragment(acc[1], 0.f);

    auto load_stage = [&](int j) {
        const uint32_t base = smu + ((j & 1) * RAW_FL) * 4;
        int k0 = j * KC;
        #pragma unroll
        for (int q = 0; q < 2; ++q) {               // A: 512 f4 tasks (2/thread)
            int i = q * 256 + tid;
            int r = i >> 3, s = (i & 7) * 4;
            CPA16(base + (r * LDS + s) * 4, A + (size_t)r * lda + k0 + s);
        }
        #pragma unroll
        for (int q = 0; q < 2; ++q) {               // W: 512 f4 tasks
            int i = q * 256 + tid;
            int r = i >> 3, s = (i & 7) * 4;
            CPA16(base + (RAW_W + r * LDS + s) * 4, W + (size_t)(n0 + r) * ldw + k0 + s);
        }
        asm volatile("cp.async.commit_group;" ::: "memory");
    };

    load_stage(0);
    if (NC > 1) load_stage(1);

    for (int j = 0; j < NC; ++j) {
        if (j + 1 < NC) asm volatile("cp.async.wait_group 1;" ::: "memory");
        else            asm volatile("cp.async.wait_group 0;" ::: "memory");
        __syncthreads();

        const float* raw = sm + (j & 1) * RAW_FL;
        float* spl = sm + SPL;
        // split A rows (2 f4/thread), straight-line float4
        #pragma unroll
        for (int q = 0; q < 2; ++q) {
            int off = q * (32 * LDS) + loff;        // +256 f4 = +32 rows
            float4 hi, lo;
            split4(*(const float4*)(raw + off), &hi, &lo);
            *(float4*)(spl + off) = hi;
            *(float4*)(spl + SP_ALO + off) = lo;
        }
        // split W rows (2 f4/thread)
        #pragma unroll
        for (int q = 0; q < 2; ++q) {
            int off = q * (32 * LDS) + loff;
            float4 hi, lo;
            split4(*(const float4*)(raw + RAW_W + off), &hi, &lo);
            *(float4*)(spl + SP_WHI + off) = hi;
            *(float4*)(spl + SP_WLO + off) = lo;
        }
        __syncthreads();

        if (j + 2 < NC) load_stage(j + 2);

        #pragma unroll
        for (int kk = 0; kk < KC / 8; ++kk) {
            wmma::fragment<wmma::matrix_a, 16, 16, 8, wmma::precision::tf32, wmma::row_major> aH[2], aL[2];
            #pragma unroll
            for (int mt = 0; mt < 2; ++mt) {
                int mr = wm * 32 + mt * 16;
                wmma::load_matrix_sync(aH[mt], spl + mr * LDS + kk * 8, LDS);
                wmma::load_matrix_sync(aL[mt], spl + SP_ALO + mr * LDS + kk * 8, LDS);
            }
            int nc = wn * 16;
            wmma::fragment<wmma::matrix_b, 16, 16, 8, wmma::precision::tf32, wmma::col_major> bH, bL;
            wmma::load_matrix_sync(bH, spl + SP_WHI + nc * LDS + kk * 8, LDS);
            wmma::load_matrix_sync(bL, spl + SP_WLO + nc * LDS + kk * 8, LDS);
            #pragma unroll
            for (int mt = 0; mt < 2; ++mt) {
                wmma::mma_sync(acc[mt], aH[mt], bH, acc[mt]);
                wmma::mma_sync(acc[mt], aH[mt], bL, acc[mt]);
                wmma::mma_sync(acc[mt], aL[mt], bH, acc[mt]);
            }
        }
        __syncthreads();
    }

    // ---- epilogue: accumulators -> smem [64][64] ----
    float* sbuf = sm;
    #pragma unroll
    for (int mt = 0; mt < 2; ++mt)
        wmma::store_matrix_sync(sbuf + (wm * 32 + mt * 16) * CTAN + wn * 16,
                                acc[mt], CTAN, wmma::mem_row_major);
    __syncthreads();

    if (outAcc) {   // gates mode
        for (int i = tid; i < 64 * CTAN; i += 256) {
            int b = i >> 6, n = i & 63;
            outAcc[(size_t)b * G3 + n0 + n] = sbuf[i];
        }
        return;
    }

    // logits mode: bias + store + per-row argmax partial
    int b = tid >> 2, cs = (tid & 3) * 16;
    float* out = outL + (size_t)b * TT * VV + (size_t)t * VV + n0;
    float bestv = -1e30f; int besti = 0;
    #pragma unroll
    for (int n = cs; n < cs + 16; n += 4) {
        float4 v = *(float4*)&sbuf[b * CTAN + n];
        float4 bi = *(const float4*)&bias[n0 + n];
        v.x += bi.x; v.y += bi.y; v.z += bi.z; v.w += bi.w;
        *(float4*)(out + n) = v;
        if (v.x > bestv) { bestv = v.x; besti = n0 + n; }
        if (v.y > bestv) { bestv = v.y; besti = n0 + n + 1; }
        if (v.z > bestv) { bestv = v.z; besti = n0 + n + 2; }
        if (v.w > bestv) { bestv = v.w; besti = n0 + n + 3; }
    }
    #pragma unroll
    for (int o = 1; o <= 2; o <<= 1) {
        float ov = __shfl_xor_sync(0xffffffffu, bestv, o);
        int   oi = __shfl_xor_sync(0xffffffffu, besti, o);
        if (ov > bestv || (ov == bestv && oi < besti)) { bestv = ov; besti = oi; }
    }
    if ((tid & 3) == 0) {
        g_pv[b * NBLK + bx] = bestv;
        g_pi[b * NBLK + bx] = besti;
    }
}

__global__ void __launch_bounds__(256, 3) k_mm_logits(const float* __restrict__ W_out,
                                                      const float* __restrict__ b_out,
                                                      float* __restrict__ outL, int t) {
    mm_core(g_h, HH, W_out, HH, HH / KC, blockIdx.x * CTAN,
            nullptr, b_out, outL, t, blockIdx.x);
}
__global__ void __launch_bounds__(256, 3) k_mm_pre(const float* __restrict__ W_ih,
                                                   const float* __restrict__ W_hh) {
    int bx = blockIdx.x;   // 144 CTAs: [0,48) ghA, [48,96) ghB, [96,144) gi
    if (bx < 48)
        mm_core(g_h, HH, W_hh, HH, 512 / KC, bx * CTAN,
                g_ghA, nullptr, nullptr, 0, 0);
    else if (bx < 96)
        mm_core(g_h + 512, HH, W_hh + 512, HH, 512 / KC, (bx - 48) * CTAN,
                g_ghB, nullptr, nullptr, 0, 0);
    else
        mm_core(g_emb, EE, W_ih, EE + HH, EE / KC, (bx - 96) * CTAN,
                g_giacc, nullptr, nullptr, 0, 0);
}
__global__ void __launch_bounds__(256, 3) k_mm_gictx(const float* __restrict__ W_ih) {
    mm_core(g_ctx, HH, W_ih + EE, EE + HH, HH / KC, blockIdx.x * CTAN,
            g_gictx, nullptr, nullptr, 0, 0);
}

// ---------------- GRU gates ----------------
__global__ void __launch_bounds__(256) k_gates(const float* __restrict__ b_ih,
                                               const float* __restrict__ b_hh,
                                               float* __restrict__ out_h) {
    int idx = blockIdx.x * 256 + threadIdx.x;   // < 65536
    int b = idx >> 10, i = idx & 1023;
    int base = b * G3;
    float gir = g_giacc[base + i]        + g_gictx[base + i]        + b_ih[i];
    float giz = g_giacc[base + 1024 + i] + g_gictx[base + 1024 + i] + b_ih[1024 + i];
    float gin = g_giacc[base + 2048 + i] + g_gictx[base + 2048 + i] + b_ih[2048 + i];
    float ghr = g_ghA[base + i]        + g_ghB[base + i]        + b_hh[i];
    float ghz = g_ghA[base + 1024 + i] + g_ghB[base + 1024 + i] + b_hh[1024 + i];
    float ghn = g_ghA[base + 2048 + i] + g_ghB[base + 2048 + i] + b_hh[2048 + i];
    float r = 1.f / (1.f + expf(-(gir + ghr)));
    float z = 1.f / (1.f + expf(-(giz + ghz)));
    float n = tanhf(gin + r * ghn);
    float hn = (1.f - z) * n + z * g_h[idx];
    g_h[idx] = hn;
    if (out_h) out_h[idx] = hn;
}

// ---------------- argmax finalize -> token + emb gather ----------------
__global__ void __launch_bounds__(256) k_amax_fin(const float* __restrict__ embt) {
    int b = blockIdx.x, tid = threadIdx.x;
    float v = -1e30f; int i = 0x7fffffff;
    for (int p = tid; p < NBLK; p += 256) {
        float pv = g_pv[b * NBLK + p]; int pi = g_pi[b * NBLK + p];
        if (pv > v || (pv == v && pi < i)) { v = pv; i = pi; }
    }
    __shared__ float sv[256]; __shared__ int si[256];
    sv[tid] = v; si[tid] = i; __syncthreads();
    for (int s = 128; s; s >>= 1) {
        if (tid < s && (sv[tid + s] > sv[tid] ||
                        (sv[tid + s] == sv[tid] && si[tid + s] < si[tid]))) {
            sv[tid] = sv[tid + s]; si[tid] = si[tid + s];
        }
        __syncthreads();
    }
    if (!tid) g_tok[b] = si[0];
    __syncthreads();
    int tok = si[0];
    for (int k = tid; k < EE; k += 256)
        g_emb[b * EE + k] = fmaxf(embt[(size_t)tok * EE + k], 0.f);
}

// ---------------- host ----------------
extern "C" void kernel_launch(void* const* d_in, const int* in_sizes, int n_in,
                              void* d_out, int out_size) {
    const float* enc   = (const float*)d_in[0];
    const float* eh    = (const float*)d_in[1];
    const float* embt  = (const float*)d_in[2];
    // d_in[3] = Wa: dead code (softmax shift invariance)
    const float* Ua    = (const float*)d_in[4];
    const float* Va    = (const float*)d_in[5];
    const float* W_ih  = (const float*)d_in[6];
    const float* W_hh  = (const float*)d_in[7];
    const float* b_ih  = (const float*)d_in[8];
    const float* b_hh  = (const float*)d_in[9];
    const float* W_out = (const float*)d_in[10];
    const float* b_out = (const float*)d_in[11];

    float* outL = (float*)d_out;
    float* outH = outL + (size_t)BB * TT * VV;
    float* outA = outH + (size_t)BB * HH;

    cudaFuncSetAttribute(k_mm_logits, cudaFuncAttributeMaxDynamicSharedMemorySize, DSMEM_BYTES);
    cudaFuncSetAttribute(k_mm_pre,    cudaFuncAttributeMaxDynamicSharedMemorySize, DSMEM_BYTES);
    cudaFuncSetAttribute(k_mm_gictx,  cudaFuncAttributeMaxDynamicSharedMemorySize, DSMEM_BYTES);

    k_init<<<(BB * HH + 255) / 256, 256>>>(eh, embt);
    k_u<<<HH / 256, 256>>>(Ua, Va);
    k_attn<<<BB, 128>>>(enc, outA);
    k_mm_gictx<<<G3 / CTAN, 256, DSMEM_BYTES>>>(W_ih);

    for (int t = 0; t < TT; ++t) {
        k_mm_pre<<<144, 256, DSMEM_BYTES>>>(W_ih, W_hh);
        k_gates<<<BB * HH / 256, 256>>>(b_ih, b_hh, (t == TT - 1) ? outH : nullptr);
        k_mm_logits<<<NBLK, 256, DSMEM_BYTES>>>(W_out, b_out, outL, t);
        if (t < TT - 1) k_amax_fin<<<BB, 256>>>(embt);
    }
}

// round 13
// speedup vs baseline: 2.4339x; 2.0189x over previous
#include <cuda_runtime.h>
#include <cstdint>
#include <math.h>

#define BB 64
#define SS 96
#define HH 1024
#define EE 512
#define VV 32000
#define TT 32
#define G3 3072
#define CTAN 128              // N tile per CTA
#define KC 32                 // K chunk (floats)
#define NBLK 250              // VV / CTAN
#define LDS 36                // smem row stride (floats) -> conflict-free fragments
// raw stage: A[64x36]=2304 + W[128x36]=4608 = 6912 floats; two stages
#define RAW_W   2304
#define RAW_FL  6912
#define DSMEM_BYTES (2 * RAW_FL * 4)      // 55296 B -> 2 CTAs/SM

// ---------------- device scratch (small, step-written only; NO big statics) ----------------
__device__ float g_u[HH];
__device__ float g_ctx[BB * HH];
__device__ float g_gictx[BB * G3];
__device__ float g_giacc[BB * G3];
__device__ float g_ghA[BB * G3];
__device__ float g_ghB[BB * G3];
__device__ float g_h[BB * HH];
__device__ float g_emb[BB * EE];
__device__ int   g_tok[BB];
__device__ float g_pv[BB * NBLK];
__device__ int   g_pi[BB * NBLK];

// ---------------- helpers ----------------
__device__ __forceinline__ float to_tf32(float v) {
    float r;
    asm("cvt.rna.tf32.f32 %0, %1;" : "=f"(r) : "f"(v));
    return r;
}
__device__ __forceinline__ uint32_t smem_u32(const void* p) {
    uint32_t a;
    asm("{ .reg .u64 t; cvta.to.shared.u64 t, %1; cvt.u32.u64 %0, t; }" : "=r"(a) : "l"(p));
    return a;
}
#define CPA16(sa, ga) \
    asm volatile("cp.async.cg.shared.global [%0], [%1], 16;" :: "r"(sa), "l"(ga))

// mma.sync m16n8k8 tf32: D(16x8,f32) += A(16x8) * B(8x8)
__device__ __forceinline__ void mma_tf32(float* d, const float* a, float b0, float b1) {
    asm volatile(
        "mma.sync.aligned.m16n8k8.row.col.f32.tf32.tf32.f32 "
        "{%0,%1,%2,%3}, {%4,%5,%6,%7}, {%8,%9}, {%0,%1,%2,%3};"
        : "+f"(d[0]), "+f"(d[1]), "+f"(d[2]), "+f"(d[3])
        : "r"(__float_as_uint(a[0])), "r"(__float_as_uint(a[1])),
          "r"(__float_as_uint(a[2])), "r"(__float_as_uint(a[3])),
          "r"(__float_as_uint(b0)),   "r"(__float_as_uint(b1)));
}

// ---------------- init ----------------
__global__ void k_init(const float* __restrict__ eh, const float* __restrict__ embt) {
    int i = blockIdx.x * blockDim.x + threadIdx.x;
    if (i < BB * HH) g_h[i] = eh[i];
    if (i < BB)      g_tok[i] = 1;
    if (i < BB * EE) g_emb[i] = fmaxf(embt[EE + (i & 511)], 0.f);   // START_TOKEN = 1
}

// ---------------- u = Ua^T Va ----------------
__global__ void __launch_bounds__(256) k_u(const float* __restrict__ Ua,
                                           const float* __restrict__ Va) {
    __shared__ float sva[HH];
    for (int i = threadIdx.x; i < HH; i += 256) sva[i] = Va[i];
    __syncthreads();
    int h = blockIdx.x * 256 + threadIdx.x;
    float acc = 0.f;
    for (int g = 0; g < HH; ++g) acc = fmaf(sva[g], Ua[(size_t)g * HH + h], acc);
    g_u[h] = acc;
}

// ---------------- attention (step-invariant) ----------------
__global__ void __launch_bounds__(128) k_attn(const float* __restrict__ keys,
                                              float* __restrict__ out_attn) {
    __shared__ float s_w[SS];
    __shared__ float s_u[HH];
    int b = blockIdx.x, tid = threadIdx.x;
    for (int i = tid; i < HH; i += 128) s_u[i] = g_u[i];
    __syncthreads();
    int warp = tid >> 5, lane = tid & 31;
    const float* kb = keys + (size_t)b * SS * HH;
    for (int s = warp; s < SS; s += 4) {
        const float* kr = kb + (size_t)s * HH;
        float acc = 0.f;
        for (int k = lane; k < HH; k += 32) acc = fmaf(kr[k], s_u[k], acc);
        #pragma unroll
        for (int o = 16; o; o >>= 1) acc += __shfl_down_sync(0xffffffffu, acc, o);
        if (!lane) s_w[s] = acc;
    }
    __syncthreads();
    if (warp == 0) {
        float m = -1e30f;
        for (int s = lane; s < SS; s += 32) m = fmaxf(m, s_w[s]);
        #pragma unroll
        for (int o = 16; o; o >>= 1) m = fmaxf(m, __shfl_xor_sync(0xffffffffu, m, o));
        float sum = 0.f;
        for (int s = lane; s < SS; s += 32) { float e = expf(s_w[s] - m); s_w[s] = e; sum += e; }
        #pragma unroll
        for (int o = 16; o; o >>= 1) sum += __shfl_xor_sync(0xffffffffu, sum, o);
        float inv = 1.f / sum;
        for (int s = lane; s < SS; s += 32) s_w[s] *= inv;
    }
    __syncthreads();
    for (int h = tid; h < HH; h += 128) {
        float acc = 0.f;
        for (int s = 0; s < SS; ++s) acc = fmaf(s_w[s], kb[(size_t)s * HH + h], acc);
        g_ctx[b * HH + h] = acc;
    }
    float* oa = out_attn + (size_t)b * TT * SS;
    for (int e = tid; e < TT * SS; e += 128) oa[e] = s_w[e % SS];
}

// ============ split-TF32 GEMM, hand mma.m16n8k8 (register split, no split-pass) ============
// out[64, 128] = A[64,K] @ W[n0..n0+127, :]^T.  acc += aH*bH + aH*bL + aL*bH (validated).
// 256 threads = 8 warps in 2(m)x4(n), warp tile 32x32.
__device__ __forceinline__ void mm_core(
    const float* __restrict__ A, int lda,
    const float* __restrict__ W, int ldw,
    int NC, int n0,
    float* __restrict__ outAcc,                                        // gates mode
    const float* __restrict__ bias, float* __restrict__ outL, int t, int bx)  // logits mode
{
    extern __shared__ float sm[];
    const int tid = threadIdx.x;
    const int wid = tid >> 5, lane = tid & 31;
    const int wm = wid >> 2, wn = wid & 3;
    const int gid = lane >> 2, tig = lane & 3;
    const uint32_t smu = smem_u32(sm);

    float d[2][4][4];
    #pragma unroll
    for (int mt = 0; mt < 2; ++mt)
        #pragma unroll
        for (int nt = 0; nt < 4; ++nt)
            #pragma unroll
            for (int e = 0; e < 4; ++e) d[mt][nt][e] = 0.f;

    auto load_stage = [&](int j) {
        const uint32_t base = smu + ((j & 1) * RAW_FL) * 4;
        int k0 = j * KC;
        #pragma unroll
        for (int q = 0; q < 2; ++q) {               // A: 512 f4 tasks (2/thread)
            int i = q * 256 + tid;
            int r = i >> 3, s = (i & 7) * 4;
            CPA16(base + (r * LDS + s) * 4, A + (size_t)r * lda + k0 + s);
        }
        #pragma unroll
        for (int q = 0; q < 4; ++q) {               // W: 1024 f4 tasks (4/thread)
            int i = q * 256 + tid;
            int r = i >> 3, s = (i & 7) * 4;
            CPA16(base + (RAW_W + r * LDS + s) * 4, W + (size_t)(n0 + r) * ldw + k0 + s);
        }
        asm volatile("cp.async.commit_group;" ::: "memory");
    };

    load_stage(0);
    if (NC > 1) load_stage(1);

    for (int j = 0; j < NC; ++j) {
        if (j + 1 < NC) asm volatile("cp.async.wait_group 1;" ::: "memory");
        else            asm volatile("cp.async.wait_group 0;" ::: "memory");
        __syncthreads();

        const float* rawA = sm + (j & 1) * RAW_FL;
        const float* rawW = rawA + RAW_W;

        #pragma unroll
        for (int kt = 0; kt < KC / 8; ++kt) {
            const int c0 = kt * 8 + tig;
            // A fragments (m16n8k8 A layout), split in registers
            float aH[2][4], aL[2][4];
            #pragma unroll
            for (int mt = 0; mt < 2; ++mt) {
                const float* ar = rawA + (wm * 32 + mt * 16 + gid) * LDS;
                float v0 = ar[c0],           v1 = ar[8 * LDS + c0];
                float v2 = ar[c0 + 4],       v3 = ar[8 * LDS + c0 + 4];
                aH[mt][0] = to_tf32(v0); aL[mt][0] = to_tf32(v0 - aH[mt][0]);
                aH[mt][1] = to_tf32(v1); aL[mt][1] = to_tf32(v1 - aH[mt][1]);
                aH[mt][2] = to_tf32(v2); aL[mt][2] = to_tf32(v2 - aH[mt][2]);
                aH[mt][3] = to_tf32(v3); aL[mt][3] = to_tf32(v3 - aH[mt][3]);
            }
            #pragma unroll
            for (int nt = 0; nt < 4; ++nt) {
                // B fragment: b0 = B[k=tig][n=gid], b1 = B[k=tig+4][n=gid]
                const float* wr = rawW + (wn * 32 + nt * 8 + gid) * LDS;
                float w0 = wr[c0], w1 = wr[c0 + 4];
                float bH0 = to_tf32(w0), bL0 = to_tf32(w0 - bH0);
                float bH1 = to_tf32(w1), bL1 = to_tf32(w1 - bH1);
                #pragma unroll
                for (int mt = 0; mt < 2; ++mt) {
                    mma_tf32(d[mt][nt], aH[mt], bH0, bH1);
                    mma_tf32(d[mt][nt], aH[mt], bL0, bL1);
                    mma_tf32(d[mt][nt], aL[mt], bH0, bH1);
                }
            }
        }
        __syncthreads();
        if (j + 2 < NC) load_stage(j + 2);
    }

    // ---- epilogue: fragments -> smem [64][128] ----
    float* sbuf = sm;
    #pragma unroll
    for (int mt = 0; mt < 2; ++mt)
        #pragma unroll
        for (int nt = 0; nt < 4; ++nt) {
            int row = wm * 32 + mt * 16 + gid;
            int col = wn * 32 + nt * 8 + 2 * tig;
            *(float2*)&sbuf[row * CTAN + col]       = make_float2(d[mt][nt][0], d[mt][nt][1]);
            *(float2*)&sbuf[(row + 8) * CTAN + col] = make_float2(d[mt][nt][2], d[mt][nt][3]);
        }
    __syncthreads();

    if (outAcc) {   // gates mode
        for (int i = tid; i < 64 * CTAN; i += 256) {
            int b = i >> 7, n = i & 127;
            outAcc[(size_t)b * G3 + n0 + n] = sbuf[i];
        }
        return;
    }

    // logits mode: bias + store + per-row argmax partial
    int b = tid >> 2, cs = (tid & 3) * 32;
    float* out = outL + (size_t)b * TT * VV + (size_t)t * VV + n0;
    float bestv = -1e30f; int besti = 0;
    #pragma unroll
    for (int n = cs; n < cs + 32; n += 4) {
        float4 v = *(float4*)&sbuf[b * CTAN + n];
        float4 bi = *(const float4*)&bias[n0 + n];
        v.x += bi.x; v.y += bi.y; v.z += bi.z; v.w += bi.w;
        *(float4*)(out + n) = v;
        if (v.x > bestv) { bestv = v.x; besti = n0 + n; }
        if (v.y > bestv) { bestv = v.y; besti = n0 + n + 1; }
        if (v.z > bestv) { bestv = v.z; besti = n0 + n + 2; }
        if (v.w > bestv) { bestv = v.w; besti = n0 + n + 3; }
    }
    #pragma unroll
    for (int o = 1; o <= 2; o <<= 1) {
        float ov = __shfl_xor_sync(0xffffffffu, bestv, o);
        int   oi = __shfl_xor_sync(0xffffffffu, besti, o);
        if (ov > bestv || (ov == bestv && oi < besti)) { bestv = ov; besti = oi; }
    }
    if ((tid & 3) == 0) {
        g_pv[b * NBLK + bx] = bestv;
        g_pi[b * NBLK + bx] = besti;
    }
}

__global__ void __launch_bounds__(256, 2) k_mm_logits(const float* __restrict__ W_out,
                                                      const float* __restrict__ b_out,
                                                      float* __restrict__ outL, int t) {
    mm_core(g_h, HH, W_out, HH, HH / KC, blockIdx.x * CTAN,
            nullptr, b_out, outL, t, blockIdx.x);
}
__global__ void __launch_bounds__(256, 2) k_mm_pre(const float* __restrict__ W_ih,
                                                   const float* __restrict__ W_hh) {
    int bx = blockIdx.x;   // 72 CTAs: [0,24) ghA (K 0-511), [24,48) ghB (K 512-1023), [48,72) gi
    if (bx < 24)
        mm_core(g_h, HH, W_hh, HH, 512 / KC, bx * CTAN,
                g_ghA, nullptr, nullptr, 0, 0);
    else if (bx < 48)
        mm_core(g_h + 512, HH, W_hh + 512, HH, 512 / KC, (bx - 24) * CTAN,
                g_ghB, nullptr, nullptr, 0, 0);
    else
        mm_core(g_emb, EE, W_ih, EE + HH, EE / KC, (bx - 48) * CTAN,
                g_giacc, nullptr, nullptr, 0, 0);
}
__global__ void __launch_bounds__(256, 2) k_mm_gictx(const float* __restrict__ W_ih) {
    mm_core(g_ctx, HH, W_ih + EE, EE + HH, HH / KC, blockIdx.x * CTAN,
            g_gictx, nullptr, nullptr, 0, 0);
}

// ---------------- GRU gates ----------------
__global__ void __launch_bounds__(256) k_gates(const float* __restrict__ b_ih,
                                               const float* __restrict__ b_hh,
                                               float* __restrict__ out_h) {
    int idx = blockIdx.x * 256 + threadIdx.x;   // < 65536
    int b = idx >> 10, i = idx & 1023;
    int base = b * G3;
    float gir = g_giacc[base + i]        + g_gictx[base + i]        + b_ih[i];
    float giz = g_giacc[base + 1024 + i] + g_gictx[base + 1024 + i] + b_ih[1024 + i];
    float gin = g_giacc[base + 2048 + i] + g_gictx[base + 2048 + i] + b_ih[2048 + i];
    float ghr = g_ghA[base + i]        + g_ghB[base + i]        + b_hh[i];
    float ghz = g_ghA[base + 1024 + i] + g_ghB[base + 1024 + i] + b_hh[1024 + i];
    float ghn = g_ghA[base + 2048 + i] + g_ghB[base + 2048 + i] + b_hh[2048 + i];
    float r = 1.f / (1.f + expf(-(gir + ghr)));
    float z = 1.f / (1.f + expf(-(giz + ghz)));
    float n = tanhf(gin + r * ghn);
    float hn = (1.f - z) * n + z * g_h[idx];
    g_h[idx] = hn;
    if (out_h) out_h[idx] = hn;
}

// ---------------- argmax finalize -> token + emb gather ----------------
__global__ void __launch_bounds__(256) k_amax_fin(const float* __restrict__ embt) {
    int b = blockIdx.x, tid = threadIdx.x;
    float v = -1e30f; int i = 0x7fffffff;
    for (int p = tid; p < NBLK; p += 256) {
        float pv = g_pv[b * NBLK + p]; int pi = g_pi[b * NBLK + p];
        if (pv > v || (pv == v && pi < i)) { v = pv; i = pi; }
    }
    __shared__ float sv[256]; __shared__ int si[256];
    sv[tid] = v; si[tid] = i; __syncthreads();
    for (int s = 128; s; s >>= 1) {
        if (tid < s && (sv[tid + s] > sv[tid] ||
                        (sv[tid + s] == sv[tid] && si[tid + s] < si[tid]))) {
            sv[tid] = sv[tid + s]; si[tid] = si[tid + s];
        }
        __syncthreads();
    }
    if (!tid) g_tok[b] = si[0];
    __syncthreads();
    int tok = si[0];
    for (int k = tid; k < EE; k += 256)
        g_emb[b * EE + k] = fmaxf(embt[(size_t)tok * EE + k], 0.f);
}

// ---------------- host ----------------
extern "C" void kernel_launch(void* const* d_in, const int* in_sizes, int n_in,
                              void* d_out, int out_size) {
    const float* enc   = (const float*)d_in[0];
    const float* eh    = (const float*)d_in[1];
    const float* embt  = (const float*)d_in[2];
    // d_in[3] = Wa: dead code (softmax shift invariance)
    const float* Ua    = (const float*)d_in[4];
    const float* Va    = (const float*)d_in[5];
    const float* W_ih  = (const float*)d_in[6];
    const float* W_hh  = (const float*)d_in[7];
    const float* b_ih  = (const float*)d_in[8];
    const float* b_hh  = (const float*)d_in[9];
    const float* W_out = (const float*)d_in[10];
    const float* b_out = (const float*)d_in[11];

    float* outL = (float*)d_out;
    float* outH = outL + (size_t)BB * TT * VV;
    float* outA = outH + (size_t)BB * HH;

    cudaFuncSetAttribute(k_mm_logits, cudaFuncAttributeMaxDynamicSharedMemorySize, DSMEM_BYTES);
    cudaFuncSetAttribute(k_mm_pre,    cudaFuncAttributeMaxDynamicSharedMemorySize, DSMEM_BYTES);
    cudaFuncSetAttribute(k_mm_gictx,  cudaFuncAttributeMaxDynamicSharedMemorySize, DSMEM_BYTES);

    k_init<<<(BB * HH + 255) / 256, 256>>>(eh, embt);
    k_u<<<HH / 256, 256>>>(Ua, Va);
    k_attn<<<BB, 128>>>(enc, outA);
    k_mm_gictx<<<G3 / CTAN, 256, DSMEM_BYTES>>>(W_ih);

    for (int t = 0; t < TT; ++t) {
        k_mm_pre<<<72, 256, DSMEM_BYTES>>>(W_ih, W_hh);
        k_gates<<<BB * HH / 256, 256>>>(b_ih, b_hh, (t == TT - 1) ? outH : nullptr);
        k_mm_logits<<<NBLK, 256, DSMEM_BYTES>>>(W_out, b_out, outL, t);
        if (t < TT - 1) k_amax_fin<<<BB, 256>>>(embt);
    }
}

// round 14
// speedup vs baseline: 2.7050x; 1.1114x over previous
#include <cuda_runtime.h>
#include <cstdint>
#include <math.h>

#define BB 64
#define SS 96
#define HH 1024
#define EE 512
#define VV 32000
#define TT 32
#define G3 3072
#define CTAN 128              // N tile per CTA
#define KC 32                 // K chunk (floats)
#define NBLK 250              // VV / CTAN
#define LDS 36                // smem row stride (floats) -> conflict-free fragments
// raw stage: A[64x36]=2304 + W[128x36]=4608 = 6912 floats; two stages
#define RAW_W   2304
#define RAW_FL  6912
#define DSMEM_BYTES (2 * RAW_FL * 4)      // 55296 B -> 2 CTAs/SM

// ---------------- device scratch (small, step-written only; NO big statics) ----------------
__device__ float g_u[HH];
__device__ float g_ctx[BB * HH];
__device__ float g_gictx[BB * G3];
__device__ float g_giA[BB * G3];
__device__ float g_giB[BB * G3];
__device__ float g_ghA[BB * G3];
__device__ float g_ghB[BB * G3];
__device__ float g_h[BB * HH];
__device__ float g_emb[BB * EE];
__device__ int   g_tok[BB];
__device__ float g_pv[BB * NBLK];
__device__ int   g_pi[BB * NBLK];

// ---------------- helpers ----------------
__device__ __forceinline__ float to_tf32(float v) {
    float r;
    asm("cvt.rna.tf32.f32 %0, %1;" : "=f"(r) : "f"(v));
    return r;
}
__device__ __forceinline__ uint32_t smem_u32(const void* p) {
    uint32_t a;
    asm("{ .reg .u64 t; cvta.to.shared.u64 t, %1; cvt.u32.u64 %0, t; }" : "=r"(a) : "l"(p));
    return a;
}
#define CPA16(sa, ga) \
    asm volatile("cp.async.cg.shared.global [%0], [%1], 16;" :: "r"(sa), "l"(ga))

// mma.sync m16n8k8 tf32: D(16x8,f32) += A(16x8) * B(8x8)
__device__ __forceinline__ void mma_tf32(float* d, const float* a, float b0, float b1) {
    asm volatile(
        "mma.sync.aligned.m16n8k8.row.col.f32.tf32.tf32.f32 "
        "{%0,%1,%2,%3}, {%4,%5,%6,%7}, {%8,%9}, {%0,%1,%2,%3};"
        : "+f"(d[0]), "+f"(d[1]), "+f"(d[2]), "+f"(d[3])
        : "r"(__float_as_uint(a[0])), "r"(__float_as_uint(a[1])),
          "r"(__float_as_uint(a[2])), "r"(__float_as_uint(a[3])),
          "r"(__float_as_uint(b0)),   "r"(__float_as_uint(b1)));
}

// ---------------- init ----------------
__global__ void k_init(const float* __restrict__ eh, const float* __restrict__ embt) {
    int i = blockIdx.x * blockDim.x + threadIdx.x;
    if (i < BB * HH) g_h[i] = eh[i];
    if (i < BB)      g_tok[i] = 1;
    if (i < BB * EE) g_emb[i] = fmaxf(embt[EE + (i & 511)], 0.f);   // START_TOKEN = 1
}

// ---------------- u = Ua^T Va ----------------
__global__ void __launch_bounds__(256) k_u(const float* __restrict__ Ua,
                                           const float* __restrict__ Va) {
    __shared__ float sva[HH];
    for (int i = threadIdx.x; i < HH; i += 256) sva[i] = Va[i];
    __syncthreads();
    int h = blockIdx.x * 256 + threadIdx.x;
    float acc = 0.f;
    for (int g = 0; g < HH; ++g) acc = fmaf(sva[g], Ua[(size_t)g * HH + h], acc);
    g_u[h] = acc;
}

// ---------------- attention (step-invariant) ----------------
__global__ void __launch_bounds__(128) k_attn(const float* __restrict__ keys,
                                              float* __restrict__ out_attn) {
    __shared__ float s_w[SS];
    __shared__ float s_u[HH];
    int b = blockIdx.x, tid = threadIdx.x;
    for (int i = tid; i < HH; i += 128) s_u[i] = g_u[i];
    __syncthreads();
    int warp = tid >> 5, lane = tid & 31;
    const float* kb = keys + (size_t)b * SS * HH;
    for (int s = warp; s < SS; s += 4) {
        const float* kr = kb + (size_t)s * HH;
        float acc = 0.f;
        for (int k = lane; k < HH; k += 32) acc = fmaf(kr[k], s_u[k], acc);
        #pragma unroll
        for (int o = 16; o; o >>= 1) acc += __shfl_down_sync(0xffffffffu, acc, o);
        if (!lane) s_w[s] = acc;
    }
    __syncthreads();
    if (warp == 0) {
        float m = -1e30f;
        for (int s = lane; s < SS; s += 32) m = fmaxf(m, s_w[s]);
        #pragma unroll
        for (int o = 16; o; o >>= 1) m = fmaxf(m, __shfl_xor_sync(0xffffffffu, m, o));
        float sum = 0.f;
        for (int s = lane; s < SS; s += 32) { float e = expf(s_w[s] - m); s_w[s] = e; sum += e; }
        #pragma unroll
        for (int o = 16; o; o >>= 1) sum += __shfl_xor_sync(0xffffffffu, sum, o);
        float inv = 1.f / sum;
        for (int s = lane; s < SS; s += 32) s_w[s] *= inv;
    }
    __syncthreads();
    for (int h = tid; h < HH; h += 128) {
        float acc = 0.f;
        for (int s = 0; s < SS; ++s) acc = fmaf(s_w[s], kb[(size_t)s * HH + h], acc);
        g_ctx[b * HH + h] = acc;
    }
    float* oa = out_attn + (size_t)b * TT * SS;
    for (int e = tid; e < TT * SS; e += 128) oa[e] = s_w[e % SS];
}

// ============ split-TF32 GEMM, hand mma.m16n8k8 (R13-validated core, unchanged) ============
__device__ __forceinline__ void mm_core(
    const float* __restrict__ A, int lda,
    const float* __restrict__ W, int ldw,
    int NC, int n0,
    float* __restrict__ outAcc,                                        // gates mode
    const float* __restrict__ bias, float* __restrict__ outL, int t, int bx)  // logits mode
{
    extern __shared__ float sm[];
    const int tid = threadIdx.x;
    const int wid = tid >> 5, lane = tid & 31;
    const int wm = wid >> 2, wn = wid & 3;
    const int gid = lane >> 2, tig = lane & 3;
    const uint32_t smu = smem_u32(sm);

    float d[2][4][4];
    #pragma unroll
    for (int mt = 0; mt < 2; ++mt)
        #pragma unroll
        for (int nt = 0; nt < 4; ++nt)
            #pragma unroll
            for (int e = 0; e < 4; ++e) d[mt][nt][e] = 0.f;

    auto load_stage = [&](int j) {
        const uint32_t base = smu + ((j & 1) * RAW_FL) * 4;
        int k0 = j * KC;
        #pragma unroll
        for (int q = 0; q < 2; ++q) {               // A: 512 f4 tasks (2/thread)
            int i = q * 256 + tid;
            int r = i >> 3, s = (i & 7) * 4;
            CPA16(base + (r * LDS + s) * 4, A + (size_t)r * lda + k0 + s);
        }
        #pragma unroll
        for (int q = 0; q < 4; ++q) {               // W: 1024 f4 tasks (4/thread)
            int i = q * 256 + tid;
            int r = i >> 3, s = (i & 7) * 4;
            CPA16(base + (RAW_W + r * LDS + s) * 4, W + (size_t)(n0 + r) * ldw + k0 + s);
        }
        asm volatile("cp.async.commit_group;" ::: "memory");
    };

    load_stage(0);
    if (NC > 1) load_stage(1);

    for (int j = 0; j < NC; ++j) {
        if (j + 1 < NC) asm volatile("cp.async.wait_group 1;" ::: "memory");
        else            asm volatile("cp.async.wait_group 0;" ::: "memory");
        __syncthreads();

        const float* rawA = sm + (j & 1) * RAW_FL;
        const float* rawW = rawA + RAW_W;

        #pragma unroll
        for (int kt = 0; kt < KC / 8; ++kt) {
            const int c0 = kt * 8 + tig;
            float aH[2][4], aL[2][4];
            #pragma unroll
            for (int mt = 0; mt < 2; ++mt) {
                const float* ar = rawA + (wm * 32 + mt * 16 + gid) * LDS;
                float v0 = ar[c0],           v1 = ar[8 * LDS + c0];
                float v2 = ar[c0 + 4],       v3 = ar[8 * LDS + c0 + 4];
                aH[mt][0] = to_tf32(v0); aL[mt][0] = to_tf32(v0 - aH[mt][0]);
                aH[mt][1] = to_tf32(v1); aL[mt][1] = to_tf32(v1 - aH[mt][1]);
                aH[mt][2] = to_tf32(v2); aL[mt][2] = to_tf32(v2 - aH[mt][2]);
                aH[mt][3] = to_tf32(v3); aL[mt][3] = to_tf32(v3 - aH[mt][3]);
            }
            #pragma unroll
            for (int nt = 0; nt < 4; ++nt) {
                const float* wr = rawW + (wn * 32 + nt * 8 + gid) * LDS;
                float w0 = wr[c0], w1 = wr[c0 + 4];
                float bH0 = to_tf32(w0), bL0 = to_tf32(w0 - bH0);
                float bH1 = to_tf32(w1), bL1 = to_tf32(w1 - bH1);
                #pragma unroll
                for (int mt = 0; mt < 2; ++mt) {
                    mma_tf32(d[mt][nt], aH[mt], bH0, bH1);
                    mma_tf32(d[mt][nt], aH[mt], bL0, bL1);
                    mma_tf32(d[mt][nt], aL[mt], bH0, bH1);
                }
            }
        }
        __syncthreads();
        if (j + 2 < NC) load_stage(j + 2);
    }

    // ---- epilogue: fragments -> smem [64][128] ----
    float* sbuf = sm;
    #pragma unroll
    for (int mt = 0; mt < 2; ++mt)
        #pragma unroll
        for (int nt = 0; nt < 4; ++nt) {
            int row = wm * 32 + mt * 16 + gid;
            int col = wn * 32 + nt * 8 + 2 * tig;
            *(float2*)&sbuf[row * CTAN + col]       = make_float2(d[mt][nt][0], d[mt][nt][1]);
            *(float2*)&sbuf[(row + 8) * CTAN + col] = make_float2(d[mt][nt][2], d[mt][nt][3]);
        }
    __syncthreads();

    if (outAcc) {   // gates mode
        for (int i = tid; i < 64 * CTAN; i += 256) {
            int b = i >> 7, n = i & 127;
            outAcc[(size_t)b * G3 + n0 + n] = sbuf[i];
        }
        return;
    }

    // logits mode: bias + store + per-row argmax partial
    int b = tid >> 2, cs = (tid & 3) * 32;
    float* out = outL + (size_t)b * TT * VV + (size_t)t * VV + n0;
    float bestv = -1e30f; int besti = 0;
    #pragma unroll
    for (int n = cs; n < cs + 32; n += 4) {
        float4 v = *(float4*)&sbuf[b * CTAN + n];
        float4 bi = *(const float4*)&bias[n0 + n];
        v.x += bi.x; v.y += bi.y; v.z += bi.z; v.w += bi.w;
        *(float4*)(out + n) = v;
        if (v.x > bestv) { bestv = v.x; besti = n0 + n; }
        if (v.y > bestv) { bestv = v.y; besti = n0 + n + 1; }
        if (v.z > bestv) { bestv = v.z; besti = n0 + n + 2; }
        if (v.w > bestv) { bestv = v.w; besti = n0 + n + 3; }
    }
    #pragma unroll
    for (int o = 1; o <= 2; o <<= 1) {
        float ov = __shfl_xor_sync(0xffffffffu, bestv, o);
        int   oi = __shfl_xor_sync(0xffffffffu, besti, o);
        if (ov > bestv || (ov == bestv && oi < besti)) { bestv = ov; besti = oi; }
    }
    if ((tid & 3) == 0) {
        g_pv[b * NBLK + bx] = bestv;
        g_pi[b * NBLK + bx] = besti;
    }
}

// gh dispatcher (used fused and standalone): bxr in [0,48)
__device__ __forceinline__ void gh_dispatch(int bxr, const float* __restrict__ W_hh) {
    if (bxr < 24)
        mm_core(g_h, HH, W_hh, HH, 512 / KC, bxr * CTAN,
                g_ghA, nullptr, nullptr, 0, 0);
    else
        mm_core(g_h + 512, HH, W_hh + 512, HH, 512 / KC, (bxr - 24) * CTAN,
                g_ghB, nullptr, nullptr, 0, 0);
}

// fused: logits (bx<250) + gh for next step (bx in [250,298))
__global__ void __launch_bounds__(256, 2) k_mm_logits(const float* __restrict__ W_out,
                                                      const float* __restrict__ b_out,
                                                      const float* __restrict__ W_hh,
                                                      float* __restrict__ outL, int t) {
    int bx = blockIdx.x;
    if (bx < NBLK)
        mm_core(g_h, HH, W_out, HH, HH / KC, bx * CTAN,
                nullptr, b_out, outL, t, bx);
    else
        gh_dispatch(bx - NBLK, W_hh);
}
__global__ void __launch_bounds__(256, 2) k_mm_gh(const float* __restrict__ W_hh) {
    gh_dispatch(blockIdx.x, W_hh);
}
// gi: emb @ W_ih[:, :EE]^T, K-split into two halves (48 CTAs)
__global__ void __launch_bounds__(256, 2) k_mm_gi(const float* __restrict__ W_ih) {
    int bx = blockIdx.x;
    if (bx < 24)
        mm_core(g_emb, EE, W_ih, EE + HH, 256 / KC, bx * CTAN,
                g_giA, nullptr, nullptr, 0, 0);
    else
        mm_core(g_emb + 256, EE, W_ih + 256, EE + HH, 256 / KC, (bx - 24) * CTAN,
                g_giB, nullptr, nullptr, 0, 0);
}
__global__ void __launch_bounds__(256, 2) k_mm_gictx(const float* __restrict__ W_ih) {
    mm_core(g_ctx, HH, W_ih + EE, EE + HH, HH / KC, blockIdx.x * CTAN,
            g_gictx, nullptr, nullptr, 0, 0);
}

// ---------------- GRU gates ----------------
__global__ void __launch_bounds__(256) k_gates(const float* __restrict__ b_ih,
                                               const float* __restrict__ b_hh,
                                               float* __restrict__ out_h) {
    int idx = blockIdx.x * 256 + threadIdx.x;   // < 65536
    int b = idx >> 10, i = idx & 1023;
    int base = b * G3;
    float gir = g_giA[base + i]        + g_giB[base + i]        + g_gictx[base + i]        + b_ih[i];
    float giz = g_giA[base + 1024 + i] + g_giB[base + 1024 + i] + g_gictx[base + 1024 + i] + b_ih[1024 + i];
    float gin = g_giA[base + 2048 + i] + g_giB[base + 2048 + i] + g_gictx[base + 2048 + i] + b_ih[2048 + i];
    float ghr = g_ghA[base + i]        + g_ghB[base + i]        + b_hh[i];
    float ghz = g_ghA[base + 1024 + i] + g_ghB[base + 1024 + i] + b_hh[1024 + i];
    float ghn = g_ghA[base + 2048 + i] + g_ghB[base + 2048 + i] + b_hh[2048 + i];
    float r = 1.f / (1.f + expf(-(gir + ghr)));
    float z = 1.f / (1.f + expf(-(giz + ghz)));
    float n = tanhf(gin + r * ghn);
    float hn = (1.f - z) * n + z * g_h[idx];
    g_h[idx] = hn;
    if (out_h) out_h[idx] = hn;
}

// ---------------- argmax finalize -> token + emb gather ----------------
__global__ void __launch_bounds__(256) k_amax_fin(const float* __restrict__ embt) {
    int b = blockIdx.x, tid = threadIdx.x;
    float v = -1e30f; int i = 0x7fffffff;
    for (int p = tid; p < NBLK; p += 256) {
        float pv = g_pv[b * NBLK + p]; int pi = g_pi[b * NBLK + p];
        if (pv > v || (pv == v && pi < i)) { v = pv; i = pi; }
    }
    __shared__ float sv[256]; __shared__ int si[256];
    sv[tid] = v; si[tid] = i; __syncthreads();
    for (int s = 128; s; s >>= 1) {
        if (tid < s && (sv[tid + s] > sv[tid] ||
                        (sv[tid + s] == sv[tid] && si[tid + s] < si[tid]))) {
            sv[tid] = sv[tid + s]; si[tid] = si[tid + s];
        }
        __syncthreads();
    }
    if (!tid) g_tok[b] = si[0];
    __syncthreads();
    int tok = si[0];
    for (int k = tid; k < EE; k += 256)
        g_emb[b * EE + k] = fmaxf(embt[(size_t)tok * EE + k], 0.f);
}

// ---------------- host ----------------
extern "C" void kernel_launch(void* const* d_in, const int* in_sizes, int n_in,
                              void* d_out, int out_size) {
    const float* enc   = (const float*)d_in[0];
    const float* eh    = (const float*)d_in[1];
    const float* embt  = (const float*)d_in[2];
    // d_in[3] = Wa: dead code (softmax shift invariance)
    const float* Ua    = (const float*)d_in[4];
    const float* Va    = (const float*)d_in[5];
    const float* W_ih  = (const float*)d_in[6];
    const float* W_hh  = (const float*)d_in[7];
    const float* b_ih  = (const float*)d_in[8];
    const float* b_hh  = (const float*)d_in[9];
    const float* W_out = (const float*)d_in[10];
    const float* b_out = (const float*)d_in[11];

    float* outL = (float*)d_out;
    float* outH = outL + (size_t)BB * TT * VV;
    float* outA = outH + (size_t)BB * HH;

    cudaFuncSetAttribute(k_mm_logits, cudaFuncAttributeMaxDynamicSharedMemorySize, DSMEM_BYTES);
    cudaFuncSetAttribute(k_mm_gh,     cudaFuncAttributeMaxDynamicSharedMemorySize, DSMEM_BYTES);
    cudaFuncSetAttribute(k_mm_gi,     cudaFuncAttributeMaxDynamicSharedMemorySize, DSMEM_BYTES);
    cudaFuncSetAttribute(k_mm_gictx,  cudaFuncAttributeMaxDynamicSharedMemorySize, DSMEM_BYTES);

    k_init<<<(BB * HH + 255) / 256, 256>>>(eh, embt);
    k_u<<<HH / 256, 256>>>(Ua, Va);
    k_attn<<<BB, 128>>>(enc, outA);
    k_mm_gictx<<<G3 / CTAN, 256, DSMEM_BYTES>>>(W_ih);
    k_mm_gh<<<48, 256, DSMEM_BYTES>>>(W_hh);       // gh(h0)
    k_mm_gi<<<48, 256, DSMEM_BYTES>>>(W_ih);       // gi(emb0)

    for (int t = 0; t < TT; ++t) {
        k_gates<<<BB * HH / 256, 256>>>(b_ih, b_hh, (t == TT - 1) ? outH : nullptr);
        k_mm_logits<<<NBLK + 48, 256, DSMEM_BYTES>>>(W_out, b_out, W_hh, outL, t);
        if (t < TT - 1) {
            k_amax_fin<<<BB, 256>>>(embt);
            k_mm_gi<<<48, 256, DSMEM_BYTES>>>(W_ih);
        }
    }
}